// round 15
// baseline (speedup 1.0000x reference)
#include <cuda_runtime.h>
#include <cuda_fp16.h>
#include <cuda_bf16.h>
#include <cuda_fp8.h>
#include <math.h>

#define BB 8
#define NN 2048
#define DD 128
#define TWO_PI_F 6.283185307179586f

// Static device scratch (no allocations allowed).
__device__ unsigned char d_Cf[(size_t)BB * NN * NN];  // coupling e4m3, m16n8k32 A-fragment layout
__device__ unsigned char d_cos8[2][BB * NN];          // ping-pong fp8 cos(theta)
__device__ unsigned char d_sin8[2][BB * NN];          // ping-pong fp8 sin(theta)

// coupling ≈ x - sqrt(x^2-1), x = max(-lz, 1+1e-7)
__device__ __forceinline__ float coupling_from_lz(float lz) {
    float x = fmaxf(-lz, 1.0f + 1e-7f);
    float t = (x - 1.0f) * (x + 1.0f);
    float xh = 0.5f * t;
    float r = __int_as_float(0x5f375a86 - (__float_as_int(t) >> 1));
    r = r * (1.5f - xh * r * r);
    r = r * (1.5f - xh * r * r);
    r = r * (1.5f - xh * r * r);
    float s = t * r;
    float c = x - s;
    return fminf(fmaxf(c, 0.0f), 1.0f);
}

#define BP 68             // smem pitch in 32-bit words (bank-exact: (4g+ti)%32 distinct)
#define SP 144            // fp8 stage pitch (bytes), 16B-aligned rows
#define BUILD_SMEM (2 * 128 * BP * 4)   // 69632 B -> 2 blocks/SM

// bf16 tensor-core build (m16n8k16), fused with fragment repack.
// 512 threads = 16 warps = 8 m-tiles x 2 n-halves; one block per 128x128
// upper-triangle tile (I,J). Halves LDS+MMA count vs the tf32 k8 version.
__global__ void __launch_bounds__(512, 2)
build_bf16_kernel(const float* __restrict__ emb) {
    extern __shared__ unsigned dynb[];
    unsigned* Asm = dynb;                 // [128][BP] words (2 bf16 each)
    unsigned* Bsm = dynb + 128 * BP;

    int t = blockIdx.x, I = 0;
    while (t >= 16 - I) { t -= 16 - I; I++; }
    int J = I + t;
    int b = blockIdx.y;
    bool offdiag = (J != I);

    int tid = threadIdx.x;
    int lane = tid & 31;
    int w = tid >> 5;
    int gid = lane >> 2, tig = lane & 3;
    int wr = w & 7, wc = w >> 3;       // m-tile 0..7, n-half 0..1

    const float* EI = emb + ((size_t)b * NN + I * 128) * DD;
    const float* EJ = emb + ((size_t)b * NN + J * 128) * DD;

    // stage both 128x128 tiles as bf16 pairs; negate time component on A side
    #pragma unroll
    for (int i = 0; i < 8; i++) {
        int idx = tid + i * 512;
        int r = idx >> 5, q = idx & 31;        // q indexes float4 (4 floats = 2 words)
        float4 v = *(const float4*)(EI + (size_t)r * DD + q * 4);
        if (q == 0) v.x = -v.x;
        __nv_bfloat162 p0 = __floats2bfloat162_rn(v.x, v.y);
        __nv_bfloat162 p1 = __floats2bfloat162_rn(v.z, v.w);
        Asm[r * BP + q * 2]     = *reinterpret_cast<unsigned*>(&p0);
        Asm[r * BP + q * 2 + 1] = *reinterpret_cast<unsigned*>(&p1);
        float4 u = *(const float4*)(EJ + (size_t)r * DD + q * 4);
        __nv_bfloat162 q0 = __floats2bfloat162_rn(u.x, u.y);
        __nv_bfloat162 q1 = __floats2bfloat162_rn(u.z, u.w);
        Bsm[r * BP + q * 2]     = *reinterpret_cast<unsigned*>(&q0);
        Bsm[r * BP + q * 2 + 1] = *reinterpret_cast<unsigned*>(&q1);
    }
    __syncthreads();

    float acc[8][4];
    #pragma unroll
    for (int nt = 0; nt < 8; nt++) {
        acc[nt][0] = 0.f; acc[nt][1] = 0.f; acc[nt][2] = 0.f; acc[nt][3] = 0.f;
    }

    int mrow = (wr << 4) + gid;        // warp's m-tile rows: mrow, mrow+8
    #pragma unroll
    for (int k0 = 0; k0 < 128; k0 += 16) {
        int kw = (k0 >> 1) + tig;      // word index of bf16 pair (k=2*tig..)
        unsigned a0 = Asm[mrow * BP + kw];
        unsigned a1 = Asm[(mrow + 8) * BP + kw];
        unsigned a2 = Asm[mrow * BP + kw + 4];
        unsigned a3 = Asm[(mrow + 8) * BP + kw + 4];
        #pragma unroll
        for (int nt = 0; nt < 8; nt++) {
            int n = wc * 64 + nt * 8 + gid;
            unsigned b0 = Bsm[n * BP + kw];
            unsigned b1 = Bsm[n * BP + kw + 4];
            asm volatile(
                "mma.sync.aligned.m16n8k16.row.col.f32.bf16.bf16.f32 "
                "{%0,%1,%2,%3}, {%4,%5,%6,%7}, {%8,%9}, {%0,%1,%2,%3};"
                : "+f"(acc[nt][0]), "+f"(acc[nt][1]), "+f"(acc[nt][2]), "+f"(acc[nt][3])
                : "r"(a0), "r"(a1), "r"(a2), "r"(a3), "r"(b0), "r"(b1));
        }
    }
    __syncthreads();

    // fp8 stage (aliases smem): stg[r][c] = C[I*128+r][J*128+c]
    unsigned char* stg = (unsigned char*)dynb;
    #pragma unroll
    for (int nt = 0; nt < 8; nt++) {
        float c0 = coupling_from_lz(acc[nt][0]);   // (mrow,   2tig)
        float c1 = coupling_from_lz(acc[nt][1]);   // (mrow,   2tig+1)
        float c2 = coupling_from_lz(acc[nt][2]);   // (mrow+8, 2tig)
        float c3 = coupling_from_lz(acc[nt][3]);   // (mrow+8, 2tig+1)
        unsigned short p01 = (unsigned short)__nv_cvt_float2_to_fp8x2(
            make_float2(c0, c1), __NV_SATFINITE, __NV_E4M3);
        unsigned short p23 = (unsigned short)__nv_cvt_float2_to_fp8x2(
            make_float2(c2, c3), __NV_SATFINITE, __NV_E4M3);
        int col = wc * 64 + nt * 8 + tig * 2;
        *(unsigned short*)(stg + mrow * SP + col)       = p01;
        *(unsigned short*)(stg + (mrow + 8) * SP + col) = p23;
    }
    __syncthreads();

    // Fragment-layout write, normal orientation (m-rows = I, k-cols = J)
    #pragma unroll
    for (int s = 0; s < 2; s++) {
        int idx = tid + s * 512;          // 0..1023 = 32 subtiles x 32 lanes
        int sub = idx >> 5, ln = idx & 31;
        int mtl = sub >> 2, ktl = sub & 3;
        int g = ln >> 2, ti = ln & 3;
        const unsigned char* base = stg + (mtl * 16 + g) * SP + ktl * 32 + ti * 4;
        uint4 o;
        o.x = *(const unsigned*)(base);
        o.y = *(const unsigned*)(base + 8 * SP);
        o.z = *(const unsigned*)(base + 16);
        o.w = *(const unsigned*)(base + 8 * SP + 16);
        size_t toff = (((size_t)(b * 128 + I * 8 + mtl)) * 64 + J * 4 + ktl) * 512
                    + (size_t)ln * 16;
        *(uint4*)(d_Cf + toff) = o;
    }

    // Mirror orientation (m-rows = J, k-cols = I): T[r][c] = stg[c][r]
    if (offdiag) {
        #pragma unroll
        for (int s = 0; s < 2; s++) {
            int idx = tid + s * 512;
            int sub = idx >> 5, ln = idx & 31;
            int mtl = sub >> 2, ktl = sub & 3;
            int g = ln >> 2, ti = ln & 3;
            int mr = mtl * 16 + g;
            int kc = ktl * 32 + ti * 4;
            unsigned wds[4];
            #pragma unroll
            for (int half = 0; half < 2; half++) {
                #pragma unroll
                for (int rr = 0; rr < 2; rr++) {
                    int r = mr + rr * 8;
                    int c = kc + half * 16;
                    unsigned x0 = stg[(c + 0) * SP + r];
                    unsigned x1 = stg[(c + 1) * SP + r];
                    unsigned x2 = stg[(c + 2) * SP + r];
                    unsigned x3 = stg[(c + 3) * SP + r];
                    wds[half * 2 + rr] = x0 | (x1 << 8) | (x2 << 16) | (x3 << 24);
                }
            }
            uint4 o = make_uint4(wds[0], wds[1], wds[2], wds[3]);
            size_t toff = (((size_t)(b * 128 + J * 8 + mtl)) * 64 + I * 4 + ktl) * 512
                        + (size_t)ln * 16;
            *(uint4*)(d_Cf + toff) = o;
        }
    }
}

__global__ void init_trig_kernel(const float* __restrict__ th) {
    int i = blockIdx.x * 256 + threadIdx.x;
    float s, c;
    sincosf(th[i], &s, &c);
    d_cos8[0][i] = (unsigned char)__nv_cvt_float_to_fp8(c, __NV_SATFINITE, __NV_E4M3);
    d_sin8[0][i] = (unsigned char)__nv_cvt_float_to_fp8(s, __NV_SATFINITE, __NV_E4M3);
}

// PERSISTENT step kernel with HW CLUSTER barriers: cluster (16,1,1) = one
// batch. barrier.cluster.arrive (release, after trig STG) / wait (acquire)
// replaces global atomics + L2 spin. No counters, no reset, no co-residency
// assumption (clusters are HW co-scheduled).
#define S_SLABS 27
#define G_SLABS 5
#define SMEM_STEPS (16 * S_SLABS * 512 + 4096 + 2048)

__global__ void __launch_bounds__(512, 1)
steps_kernel(const float* __restrict__ th_in,
             float* __restrict__ th_out,
             const float* __restrict__ omega) {
    extern __shared__ __align__(16) unsigned char dyn[];
    unsigned char* scC = dyn;                                 // 16*27*512
    unsigned* shCos = (unsigned*)(dyn + 16 * S_SLABS * 512);  // 512 words
    unsigned* shSin = shCos + 512;
    float* shPC = (float*)(shSin + 512);                      // [2][128]
    float* shPS = shPC + 256;

    int rg = blockIdx.x, b = blockIdx.y;
    int tid = threadIdx.x;
    int w = tid >> 5, lane = tid & 31;
    int gid = lane >> 2, tig = lane & 3;
    int mtl = w & 7, kq = w >> 3;

    int mt = rg * 8 + mtl;
    const uint4* Af = (const uint4*)(d_Cf
        + (((size_t)(b * 128 + mt)) * 64 + kq * 32) * 512) + lane;
    int bbase2 = kq * 256 + tig * 2;   // paired layout index

    // one-time stage: 27 slabs/warp into smem
    unsigned char* myC = scC + (size_t)(w * S_SLABS) * 512 + lane * 16;
    #pragma unroll
    for (int i = 0; i < S_SLABS; i++)
        *(uint4*)(myC + i * 512) = Af[i * 32];

    // global-slab register pipeline (step-invariant addresses)
    uint4 g[G_SLABS];
    #pragma unroll
    for (int i = 0; i < G_SLABS; i++) g[i] = Af[(S_SLABS + i) * 32];

    // register-resident oscillator state (tid < 128)
    int gi = b * NN + rg * 128 + tid;
    float th = 0.f, om = 0.f, sn = 0.f, cn = 0.f;
    if (tid < 128) {
        th = th_in[gi];
        om = omega[rg * 128 + tid];
        __sincosf(th, &sn, &cn);
    }

    // permuted staging index: slab-local words reordered 0,4,1,5,2,6,3,7
    int slab = tid >> 3, pos = tid & 7;
    int permIdx = slab * 8 + ((pos & 3) << 1) + (pos >> 2);

    for (int k = 0; k < 16; k++) {
        if (k > 0)
            asm volatile("barrier.cluster.wait.aligned;" ::: "memory");

        // stage this batch's trig (buffer k&1), paired word order
        {
            const unsigned* gc = (const unsigned*)(d_cos8[k & 1] + (size_t)b * NN);
            const unsigned* gs = (const unsigned*)(d_sin8[k & 1] + (size_t)b * NN);
            shCos[permIdx] = __ldcg(gc + tid);
            shSin[permIdx] = __ldcg(gs + tid);
        }
        __syncthreads();

        const unsigned* bp = (gid == 1) ? shSin : shCos;

        // dual accumulator sets break the MMA RAW chain
        float a0 = 0.f, a1 = 0.f, a2 = 0.f, a3 = 0.f;
        float e0 = 0.f, e1 = 0.f, e2 = 0.f, e3 = 0.f;

        #pragma unroll
        for (int it = 0; it < S_SLABS; it++) {
            uint4 f = *(const uint4*)(myC + it * 512);
            uint2 bw = *(const uint2*)(bp + bbase2 + it * 8);
            if (it & 1)
                asm volatile(
                    "mma.sync.aligned.m16n8k32.row.col.f32.e4m3.e4m3.f32 "
                    "{%0,%1,%2,%3}, {%4,%5,%6,%7}, {%8,%9}, {%0,%1,%2,%3};"
                    : "+f"(e0), "+f"(e1), "+f"(e2), "+f"(e3)
                    : "r"(f.x), "r"(f.y), "r"(f.z), "r"(f.w), "r"(bw.x), "r"(bw.y));
            else
                asm volatile(
                    "mma.sync.aligned.m16n8k32.row.col.f32.e4m3.e4m3.f32 "
                    "{%0,%1,%2,%3}, {%4,%5,%6,%7}, {%8,%9}, {%0,%1,%2,%3};"
                    : "+f"(a0), "+f"(a1), "+f"(a2), "+f"(a3)
                    : "r"(f.x), "r"(f.y), "r"(f.z), "r"(f.w), "r"(bw.x), "r"(bw.y));
        }
        #pragma unroll
        for (int j = 0; j < G_SLABS; j++) {
            uint4 f = g[j];
            g[j] = Af[(S_SLABS + j) * 32];        // prefetch for next step
            int it = S_SLABS + j;
            uint2 bw = *(const uint2*)(bp + bbase2 + it * 8);
            if (it & 1)
                asm volatile(
                    "mma.sync.aligned.m16n8k32.row.col.f32.e4m3.e4m3.f32 "
                    "{%0,%1,%2,%3}, {%4,%5,%6,%7}, {%8,%9}, {%0,%1,%2,%3};"
                    : "+f"(e0), "+f"(e1), "+f"(e2), "+f"(e3)
                    : "r"(f.x), "r"(f.y), "r"(f.z), "r"(f.w), "r"(bw.x), "r"(bw.y));
            else
                asm volatile(
                    "mma.sync.aligned.m16n8k32.row.col.f32.e4m3.e4m3.f32 "
                    "{%0,%1,%2,%3}, {%4,%5,%6,%7}, {%8,%9}, {%0,%1,%2,%3};"
                    : "+f"(a0), "+f"(a1), "+f"(a2), "+f"(a3)
                    : "r"(f.x), "r"(f.y), "r"(f.z), "r"(f.w), "r"(bw.x), "r"(bw.y));
        }

        float d0 = a0 + e0, d1 = a1 + e1, d2 = a2 + e2, d3 = a3 + e3;

        if (tig == 0) {
            int lr = mtl * 16 + gid;
            shPC[kq * 128 + lr]     = d0;
            shPS[kq * 128 + lr]     = d1;
            shPC[kq * 128 + lr + 8] = d2;
            shPS[kq * 128 + lr + 8] = d3;
        }
        __syncthreads();

        if (tid < 128) {
            float yc = shPC[tid] + shPC[128 + tid];   // fixed order -> deterministic
            float ys = shPS[tid] + shPS[128 + tid];
            float csum = sn * yc - cn * ys;
            float dth = om + (1.0f / NN) * csum;
            float thn = th + 0.1f * dth;
            // exact fmod for |x| < 2*2pi with truncation-toward-zero semantics
            if (thn >= TWO_PI_F) thn -= TWO_PI_F;     // Sterbenz-exact
            th = thn;
            __sincosf(th, &sn, &cn);
            if (k < 15) {
                d_cos8[(k + 1) & 1][gi] =
                    (unsigned char)__nv_cvt_float_to_fp8(cn, __NV_SATFINITE, __NV_E4M3);
                d_sin8[(k + 1) & 1][gi] =
                    (unsigned char)__nv_cvt_float_to_fp8(sn, __NV_SATFINITE, __NV_E4M3);
            } else {
                th_out[gi] = th;
            }
        }
        // arrive releases this thread's trig writes; barrier completes only
        // when every thread of every CTA in the cluster arrived.
        if (k < 15)
            asm volatile("barrier.cluster.arrive.aligned;" ::: "memory");
    }
}

extern "C" void kernel_launch(void* const* d_in, const int* in_sizes, int n_in,
                              void* d_out, int out_size) {
    const float* initial = (const float*)d_in[0];   // (B,N)
    const float* emb     = (const float*)d_in[1];   // (B,N,D)
    const float* omega   = (const float*)d_in[2];   // (N,)
    float* out = (float*)d_out;                     // (B,N)

    cudaFuncSetAttribute(build_bf16_kernel,
                         cudaFuncAttributeMaxDynamicSharedMemorySize, BUILD_SMEM);
    cudaFuncSetAttribute(steps_kernel,
                         cudaFuncAttributeMaxDynamicSharedMemorySize, SMEM_STEPS);
    cudaFuncSetAttribute(steps_kernel,
                         cudaFuncAttributeNonPortableClusterSizeAllowed, 1);

    dim3 bgrid(136, BB);                            // upper-triangle 128-tiles
    build_bf16_kernel<<<bgrid, 512, BUILD_SMEM>>>(emb);

    init_trig_kernel<<<BB * NN / 256, 256>>>(initial);

    cudaLaunchConfig_t cfg = {};
    cfg.gridDim = dim3(16, BB);
    cfg.blockDim = dim3(512);
    cfg.dynamicSmemBytes = SMEM_STEPS;
    cudaLaunchAttribute attrs[1];
    attrs[0].id = cudaLaunchAttributeClusterDimension;
    attrs[0].val.clusterDim.x = 16;                 // one cluster per batch
    attrs[0].val.clusterDim.y = 1;
    attrs[0].val.clusterDim.z = 1;
    cfg.attrs = attrs;
    cfg.numAttrs = 1;
    cudaLaunchKernelEx(&cfg, steps_kernel, initial, out, omega);
}

// round 16
// speedup vs baseline: 1.4880x; 1.4880x over previous
#include <cuda_runtime.h>
#include <cuda_fp16.h>
#include <cuda_bf16.h>
#include <cuda_fp8.h>
#include <math.h>

#define BB 8
#define NN 2048
#define DD 128
#define TWO_PI_F 6.283185307179586f

// Static device scratch (no allocations allowed).
__device__ unsigned char d_Cf[(size_t)BB * NN * NN];  // coupling e4m3, m16n8k32 A-fragment layout
__device__ unsigned char d_cos8[2][BB * NN];          // ping-pong fp8 cos(theta)
__device__ unsigned char d_sin8[2][BB * NN];          // ping-pong fp8 sin(theta)
__device__ unsigned d_barStep[BB];                    // per-batch step barriers (BSS=0)
__device__ int d_barExit;                             // exit counter for reset

// coupling ≈ x - sqrt(x^2-1), x = max(-lz, 1+1e-7)
__device__ __forceinline__ float coupling_from_lz(float lz) {
    float x = fmaxf(-lz, 1.0f + 1e-7f);
    float t = (x - 1.0f) * (x + 1.0f);
    float xh = 0.5f * t;
    float r = __int_as_float(0x5f375a86 - (__float_as_int(t) >> 1));
    r = r * (1.5f - xh * r * r);
    r = r * (1.5f - xh * r * r);
    r = r * (1.5f - xh * r * r);
    float s = t * r;
    float c = x - s;
    return fminf(fmaxf(c, 0.0f), 1.0f);
}

#define BP 68             // smem pitch in 32-bit words (bank-exact fragment LDS)
#define SP 144            // fp8 stage pitch (bytes), 16B-aligned rows
#define BUILD_SMEM (2 * 128 * BP * 4)   // 69632 B -> 2 blocks/SM

// bf16 tensor-core build (m16n8k16), fused with fragment repack.
// 512 threads = 16 warps = 8 m-tiles x 2 n-halves; one block per 128x128
// upper-triangle tile (I,J). (Measured 39.8us on GB300.)
__global__ void __launch_bounds__(512, 2)
build_bf16_kernel(const float* __restrict__ emb) {
    extern __shared__ unsigned dynb[];
    unsigned* Asm = dynb;                 // [128][BP] words (2 bf16 each)
    unsigned* Bsm = dynb + 128 * BP;

    int t = blockIdx.x, I = 0;
    while (t >= 16 - I) { t -= 16 - I; I++; }
    int J = I + t;
    int b = blockIdx.y;
    bool offdiag = (J != I);

    int tid = threadIdx.x;
    int lane = tid & 31;
    int w = tid >> 5;
    int gid = lane >> 2, tig = lane & 3;
    int wr = w & 7, wc = w >> 3;       // m-tile 0..7, n-half 0..1

    const float* EI = emb + ((size_t)b * NN + I * 128) * DD;
    const float* EJ = emb + ((size_t)b * NN + J * 128) * DD;

    // stage both 128x128 tiles as bf16 pairs; negate time component on A side
    #pragma unroll
    for (int i = 0; i < 8; i++) {
        int idx = tid + i * 512;
        int r = idx >> 5, q = idx & 31;        // q indexes float4 (4 floats = 2 words)
        float4 v = *(const float4*)(EI + (size_t)r * DD + q * 4);
        if (q == 0) v.x = -v.x;
        __nv_bfloat162 p0 = __floats2bfloat162_rn(v.x, v.y);
        __nv_bfloat162 p1 = __floats2bfloat162_rn(v.z, v.w);
        Asm[r * BP + q * 2]     = *reinterpret_cast<unsigned*>(&p0);
        Asm[r * BP + q * 2 + 1] = *reinterpret_cast<unsigned*>(&p1);
        float4 u = *(const float4*)(EJ + (size_t)r * DD + q * 4);
        __nv_bfloat162 q0 = __floats2bfloat162_rn(u.x, u.y);
        __nv_bfloat162 q1 = __floats2bfloat162_rn(u.z, u.w);
        Bsm[r * BP + q * 2]     = *reinterpret_cast<unsigned*>(&q0);
        Bsm[r * BP + q * 2 + 1] = *reinterpret_cast<unsigned*>(&q1);
    }
    __syncthreads();

    float acc[8][4];
    #pragma unroll
    for (int nt = 0; nt < 8; nt++) {
        acc[nt][0] = 0.f; acc[nt][1] = 0.f; acc[nt][2] = 0.f; acc[nt][3] = 0.f;
    }

    int mrow = (wr << 4) + gid;        // warp's m-tile rows: mrow, mrow+8
    #pragma unroll
    for (int k0 = 0; k0 < 128; k0 += 16) {
        int kw = (k0 >> 1) + tig;      // word index of bf16 pair
        unsigned a0 = Asm[mrow * BP + kw];
        unsigned a1 = Asm[(mrow + 8) * BP + kw];
        unsigned a2 = Asm[mrow * BP + kw + 4];
        unsigned a3 = Asm[(mrow + 8) * BP + kw + 4];
        #pragma unroll
        for (int nt = 0; nt < 8; nt++) {
            int n = wc * 64 + nt * 8 + gid;
            unsigned b0 = Bsm[n * BP + kw];
            unsigned b1 = Bsm[n * BP + kw + 4];
            asm volatile(
                "mma.sync.aligned.m16n8k16.row.col.f32.bf16.bf16.f32 "
                "{%0,%1,%2,%3}, {%4,%5,%6,%7}, {%8,%9}, {%0,%1,%2,%3};"
                : "+f"(acc[nt][0]), "+f"(acc[nt][1]), "+f"(acc[nt][2]), "+f"(acc[nt][3])
                : "r"(a0), "r"(a1), "r"(a2), "r"(a3), "r"(b0), "r"(b1));
        }
    }
    __syncthreads();

    // fp8 stage (aliases smem): stg[r][c] = C[I*128+r][J*128+c]
    unsigned char* stg = (unsigned char*)dynb;
    #pragma unroll
    for (int nt = 0; nt < 8; nt++) {
        float c0 = coupling_from_lz(acc[nt][0]);
        float c1 = coupling_from_lz(acc[nt][1]);
        float c2 = coupling_from_lz(acc[nt][2]);
        float c3 = coupling_from_lz(acc[nt][3]);
        unsigned short p01 = (unsigned short)__nv_cvt_float2_to_fp8x2(
            make_float2(c0, c1), __NV_SATFINITE, __NV_E4M3);
        unsigned short p23 = (unsigned short)__nv_cvt_float2_to_fp8x2(
            make_float2(c2, c3), __NV_SATFINITE, __NV_E4M3);
        int col = wc * 64 + nt * 8 + tig * 2;
        *(unsigned short*)(stg + mrow * SP + col)       = p01;
        *(unsigned short*)(stg + (mrow + 8) * SP + col) = p23;
    }
    __syncthreads();

    // Fragment-layout write, normal orientation (m-rows = I, k-cols = J)
    #pragma unroll
    for (int s = 0; s < 2; s++) {
        int idx = tid + s * 512;          // 0..1023 = 32 subtiles x 32 lanes
        int sub = idx >> 5, ln = idx & 31;
        int mtl = sub >> 2, ktl = sub & 3;
        int g = ln >> 2, ti = ln & 3;
        const unsigned char* base = stg + (mtl * 16 + g) * SP + ktl * 32 + ti * 4;
        uint4 o;
        o.x = *(const unsigned*)(base);
        o.y = *(const unsigned*)(base + 8 * SP);
        o.z = *(const unsigned*)(base + 16);
        o.w = *(const unsigned*)(base + 8 * SP + 16);
        size_t toff = (((size_t)(b * 128 + I * 8 + mtl)) * 64 + J * 4 + ktl) * 512
                    + (size_t)ln * 16;
        *(uint4*)(d_Cf + toff) = o;
    }

    // Mirror orientation (m-rows = J, k-cols = I): T[r][c] = stg[c][r]
    if (offdiag) {
        #pragma unroll
        for (int s = 0; s < 2; s++) {
            int idx = tid + s * 512;
            int sub = idx >> 5, ln = idx & 31;
            int mtl = sub >> 2, ktl = sub & 3;
            int g = ln >> 2, ti = ln & 3;
            int mr = mtl * 16 + g;
            int kc = ktl * 32 + ti * 4;
            unsigned wds[4];
            #pragma unroll
            for (int half = 0; half < 2; half++) {
                #pragma unroll
                for (int rr = 0; rr < 2; rr++) {
                    int r = mr + rr * 8;
                    int c = kc + half * 16;
                    unsigned x0 = stg[(c + 0) * SP + r];
                    unsigned x1 = stg[(c + 1) * SP + r];
                    unsigned x2 = stg[(c + 2) * SP + r];
                    unsigned x3 = stg[(c + 3) * SP + r];
                    wds[half * 2 + rr] = x0 | (x1 << 8) | (x2 << 16) | (x3 << 24);
                }
            }
            uint4 o = make_uint4(wds[0], wds[1], wds[2], wds[3]);
            size_t toff = (((size_t)(b * 128 + J * 8 + mtl)) * 64 + I * 4 + ktl) * 512
                        + (size_t)ln * 16;
            *(uint4*)(d_Cf + toff) = o;
        }
    }
}

__global__ void init_trig_kernel(const float* __restrict__ th) {
    int i = blockIdx.x * 256 + threadIdx.x;
    float s, c;
    sincosf(th[i], &s, &c);
    d_cos8[0][i] = (unsigned char)__nv_cvt_float_to_fp8(c, __NV_SATFINITE, __NV_E4M3);
    d_sin8[0][i] = (unsigned char)__nv_cvt_float_to_fp8(s, __NV_SATFINITE, __NV_E4M3);
}

// PERSISTENT step kernel (R14 software-barrier version — the cluster barrier
// regressed because barrier.cluster emits CCTL.IVALL, flushing the L1-resident
// C stream every step). Per-batch counter + red.release + acquire spin leaves
// L1 intact. smem-pinned C (27/32 slabs), paired-LDS trig, no threadfence.
#define S_SLABS 27
#define G_SLABS 5
#define SMEM_STEPS (16 * S_SLABS * 512 + 4096 + 2048)

__global__ void __launch_bounds__(512, 1)
steps_kernel(const float* __restrict__ th_in,
             float* __restrict__ th_out,
             const float* __restrict__ omega) {
    extern __shared__ __align__(16) unsigned char dyn[];
    unsigned char* scC = dyn;                                 // 16*27*512
    unsigned* shCos = (unsigned*)(dyn + 16 * S_SLABS * 512);  // 512 words
    unsigned* shSin = shCos + 512;
    float* shPC = (float*)(shSin + 512);                      // [2][128]
    float* shPS = shPC + 256;

    int rg = blockIdx.x, b = blockIdx.y;
    int tid = threadIdx.x;
    int w = tid >> 5, lane = tid & 31;
    int gid = lane >> 2, tig = lane & 3;
    int mtl = w & 7, kq = w >> 3;

    int mt = rg * 8 + mtl;
    const uint4* Af = (const uint4*)(d_Cf
        + (((size_t)(b * 128 + mt)) * 64 + kq * 32) * 512) + lane;
    int bbase2 = kq * 256 + tig * 2;   // paired layout index

    // one-time stage: 27 slabs/warp into smem
    unsigned char* myC = scC + (size_t)(w * S_SLABS) * 512 + lane * 16;
    #pragma unroll
    for (int i = 0; i < S_SLABS; i++)
        *(uint4*)(myC + i * 512) = Af[i * 32];

    // global-slab register pipeline (step-invariant addresses)
    uint4 g[G_SLABS];
    #pragma unroll
    for (int i = 0; i < G_SLABS; i++) g[i] = Af[(S_SLABS + i) * 32];

    // register-resident oscillator state (tid < 128)
    int gi = b * NN + rg * 128 + tid;
    float th = 0.f, om = 0.f, sn = 0.f, cn = 0.f;
    if (tid < 128) {
        th = th_in[gi];
        om = omega[rg * 128 + tid];
        __sincosf(th, &sn, &cn);
    }

    // permuted staging index: slab-local words reordered 0,4,1,5,2,6,3,7
    int slab = tid >> 3, pos = tid & 7;
    int permIdx = slab * 8 + ((pos & 3) << 1) + (pos >> 2);

    for (int k = 0; k < 16; k++) {
        if (k > 0) {
            if (tid == 0) {
                unsigned target = 16u * (unsigned)k;
                unsigned v;
                do {
                    asm volatile("ld.acquire.gpu.global.u32 %0, [%1];"
                                 : "=r"(v) : "l"(&d_barStep[b]) : "memory");
                } while (v < target);
            }
            __syncthreads();
        }

        // stage this batch's trig (buffer k&1), paired word order
        {
            const unsigned* gc = (const unsigned*)(d_cos8[k & 1] + (size_t)b * NN);
            const unsigned* gs = (const unsigned*)(d_sin8[k & 1] + (size_t)b * NN);
            shCos[permIdx] = __ldcg(gc + tid);
            shSin[permIdx] = __ldcg(gs + tid);
        }
        __syncthreads();

        const unsigned* bp = (gid == 1) ? shSin : shCos;

        // dual accumulator sets break the MMA RAW chain
        float a0 = 0.f, a1 = 0.f, a2 = 0.f, a3 = 0.f;
        float e0 = 0.f, e1 = 0.f, e2 = 0.f, e3 = 0.f;

        #pragma unroll
        for (int it = 0; it < S_SLABS; it++) {
            uint4 f = *(const uint4*)(myC + it * 512);
            uint2 bw = *(const uint2*)(bp + bbase2 + it * 8);
            if (it & 1)
                asm volatile(
                    "mma.sync.aligned.m16n8k32.row.col.f32.e4m3.e4m3.f32 "
                    "{%0,%1,%2,%3}, {%4,%5,%6,%7}, {%8,%9}, {%0,%1,%2,%3};"
                    : "+f"(e0), "+f"(e1), "+f"(e2), "+f"(e3)
                    : "r"(f.x), "r"(f.y), "r"(f.z), "r"(f.w), "r"(bw.x), "r"(bw.y));
            else
                asm volatile(
                    "mma.sync.aligned.m16n8k32.row.col.f32.e4m3.e4m3.f32 "
                    "{%0,%1,%2,%3}, {%4,%5,%6,%7}, {%8,%9}, {%0,%1,%2,%3};"
                    : "+f"(a0), "+f"(a1), "+f"(a2), "+f"(a3)
                    : "r"(f.x), "r"(f.y), "r"(f.z), "r"(f.w), "r"(bw.x), "r"(bw.y));
        }
        #pragma unroll
        for (int j = 0; j < G_SLABS; j++) {
            uint4 f = g[j];
            g[j] = Af[(S_SLABS + j) * 32];        // prefetch for next step
            int it = S_SLABS + j;
            uint2 bw = *(const uint2*)(bp + bbase2 + it * 8);
            if (it & 1)
                asm volatile(
                    "mma.sync.aligned.m16n8k32.row.col.f32.e4m3.e4m3.f32 "
                    "{%0,%1,%2,%3}, {%4,%5,%6,%7}, {%8,%9}, {%0,%1,%2,%3};"
                    : "+f"(e0), "+f"(e1), "+f"(e2), "+f"(e3)
                    : "r"(f.x), "r"(f.y), "r"(f.z), "r"(f.w), "r"(bw.x), "r"(bw.y));
            else
                asm volatile(
                    "mma.sync.aligned.m16n8k32.row.col.f32.e4m3.e4m3.f32 "
                    "{%0,%1,%2,%3}, {%4,%5,%6,%7}, {%8,%9}, {%0,%1,%2,%3};"
                    : "+f"(a0), "+f"(a1), "+f"(a2), "+f"(a3)
                    : "r"(f.x), "r"(f.y), "r"(f.z), "r"(f.w), "r"(bw.x), "r"(bw.y));
        }

        float d0 = a0 + e0, d1 = a1 + e1, d2 = a2 + e2, d3 = a3 + e3;

        if (tig == 0) {
            int lr = mtl * 16 + gid;
            shPC[kq * 128 + lr]     = d0;
            shPS[kq * 128 + lr]     = d1;
            shPC[kq * 128 + lr + 8] = d2;
            shPS[kq * 128 + lr + 8] = d3;
        }
        __syncthreads();

        if (tid < 128) {
            float yc = shPC[tid] + shPC[128 + tid];   // fixed order -> deterministic
            float ys = shPS[tid] + shPS[128 + tid];
            float csum = sn * yc - cn * ys;
            float dth = om + (1.0f / NN) * csum;
            float thn = th + 0.1f * dth;
            if (thn >= TWO_PI_F) thn -= TWO_PI_F;     // exact in-range fmod
            th = thn;
            __sincosf(th, &sn, &cn);
            if (k < 15) {
                d_cos8[(k + 1) & 1][gi] =
                    (unsigned char)__nv_cvt_float_to_fp8(cn, __NV_SATFINITE, __NV_E4M3);
                d_sin8[(k + 1) & 1][gi] =
                    (unsigned char)__nv_cvt_float_to_fp8(sn, __NV_SATFINITE, __NV_E4M3);
            } else {
                th_out[gi] = th;
            }
        }
        __syncthreads();   // orders trig writes before the release below
        if (k < 15 && tid == 0)
            asm volatile("red.release.gpu.global.add.u32 [%0], %1;"
                         :: "l"(&d_barStep[b]), "r"(1u) : "memory");
    }

    // exit: last block resets counters so every graph replay starts clean
    __syncthreads();
    if (tid == 0) {
        int old = atomicAdd(&d_barExit, 1);
        if (old == 127) {
            #pragma unroll
            for (int i = 0; i < BB; i++) atomicExch(&d_barStep[i], 0u);
            atomicExch(&d_barExit, 0);
        }
    }
}

extern "C" void kernel_launch(void* const* d_in, const int* in_sizes, int n_in,
                              void* d_out, int out_size) {
    const float* initial = (const float*)d_in[0];   // (B,N)
    const float* emb     = (const float*)d_in[1];   // (B,N,D)
    const float* omega   = (const float*)d_in[2];   // (N,)
    float* out = (float*)d_out;                     // (B,N)

    cudaFuncSetAttribute(build_bf16_kernel,
                         cudaFuncAttributeMaxDynamicSharedMemorySize, BUILD_SMEM);
    cudaFuncSetAttribute(steps_kernel,
                         cudaFuncAttributeMaxDynamicSharedMemorySize, SMEM_STEPS);

    dim3 bgrid(136, BB);                            // upper-triangle 128-tiles
    build_bf16_kernel<<<bgrid, 512, BUILD_SMEM>>>(emb);

    init_trig_kernel<<<BB * NN / 256, 256>>>(initial);

    dim3 sgrid(16, BB);                             // 128 blocks, all co-resident
    steps_kernel<<<sgrid, 512, SMEM_STEPS>>>(initial, out, omega);
}